// round 9
// baseline (speedup 1.0000x reference)
#include <cuda_runtime.h>
#include <cuda_bf16.h>
#include <cuda_fp16.h>
#include <cstdint>

#define DM 1024
#define NH 16
#define HD 64
#define BB 2
#define TT 2048
#define MM (BB*TT)   // 4096 rows
#define WSZ ((size_t)DM * DM)

// Scratch. Q,K,V fp32 in [B,H,T,D]; x & weights & attn-out pre-split bf16 hi/lo.
__device__ float g_q[(size_t)MM * DM];
__device__ float g_k[(size_t)MM * DM];
__device__ float g_v[(size_t)MM * DM];
__device__ __nv_bfloat16 g_xh[(size_t)MM * DM];
__device__ __nv_bfloat16 g_xl[(size_t)MM * DM];
__device__ __nv_bfloat16 g_wh[4 * WSZ];
__device__ __nv_bfloat16 g_wl[4 * WSZ];
__device__ __nv_bfloat16 g_ah[(size_t)MM * DM];
__device__ __nv_bfloat16 g_al[(size_t)MM * DM];

__device__ __forceinline__ uint32_t smem_addr_u32(const void* smem_ptr) {
    uint32_t addr;
    asm("{ .reg .u64 tmp; cvta.to.shared.u64 tmp, %1; cvt.u32.u64 %0, tmp; }"
        : "=r"(addr) : "l"(smem_ptr));
    return addr;
}

#define SMEM_SWIZZLE_128B(byte_offset) \
    ((byte_offset) ^ (((byte_offset) >> 3) & 0x70))

__device__ __forceinline__ void cp_async16(uint32_t dst, const void* src) {
    asm volatile("cp.async.cg.shared.global [%0], [%1], 16;"
                 :: "r"(dst), "l"(src));
}
#define CP_COMMIT() asm volatile("cp.async.commit_group;" ::: "memory")
#define CP_WAIT0()  asm volatile("cp.async.wait_group 0;"  ::: "memory")

__device__ __forceinline__ void ldmatrix_x4(uint32_t& r0, uint32_t& r1,
                                            uint32_t& r2, uint32_t& r3,
                                            uint32_t addr) {
    asm volatile("ldmatrix.sync.aligned.m8n8.x4.shared.b16 {%0,%1,%2,%3}, [%4];"
                 : "=r"(r0), "=r"(r1), "=r"(r2), "=r"(r3) : "r"(addr));
}

__device__ __forceinline__ void ldmatrix_x4_trans(uint32_t& r0, uint32_t& r1,
                                                  uint32_t& r2, uint32_t& r3,
                                                  uint32_t addr) {
    asm volatile("ldmatrix.sync.aligned.m8n8.x4.trans.shared.b16 {%0,%1,%2,%3}, [%4];"
                 : "=r"(r0), "=r"(r1), "=r"(r2), "=r"(r3) : "r"(addr));
}

__device__ __forceinline__ void mma_bf16(float* d, const uint32_t* a,
                                         uint32_t b0, uint32_t b1) {
    asm volatile(
        "mma.sync.aligned.m16n8k16.row.col.f32.bf16.bf16.f32 "
        "{%0,%1,%2,%3}, {%4,%5,%6,%7}, {%8,%9}, {%0,%1,%2,%3};"
        : "+f"(d[0]), "+f"(d[1]), "+f"(d[2]), "+f"(d[3])
        : "r"(a[0]), "r"(a[1]), "r"(a[2]), "r"(a[3]), "r"(b0), "r"(b1));
}

__device__ __forceinline__ void mma_f16(float* d, const uint32_t* a,
                                        uint32_t b0, uint32_t b1) {
    asm volatile(
        "mma.sync.aligned.m16n8k16.row.col.f32.f16.f16.f32 "
        "{%0,%1,%2,%3}, {%4,%5,%6,%7}, {%8,%9}, {%0,%1,%2,%3};"
        : "+f"(d[0]), "+f"(d[1]), "+f"(d[2]), "+f"(d[3])
        : "r"(a[0]), "r"(a[1]), "r"(a[2]), "r"(a[3]), "r"(b0), "r"(b1));
}

__device__ __forceinline__ uint32_t pack_bf2(__nv_bfloat16 a, __nv_bfloat16 b) {
    return ((uint32_t)__bfloat16_as_ushort(b) << 16) | (uint32_t)__bfloat16_as_ushort(a);
}

__device__ __forceinline__ uint32_t pack_h2(float a, float b) {
    __half2 h = __floats2half2_rn(a, b);
    return *(uint32_t*)&h;
}

// fp32 -> fp16 hi/lo split (flash path)
__device__ __forceinline__ void split_store_h(char* phi, char* plo, uint32_t off,
                                              float4 v) {
    __half h0 = __float2half_rn(v.x), h1 = __float2half_rn(v.y);
    __half h2 = __float2half_rn(v.z), h3 = __float2half_rn(v.w);
    float l0 = v.x - __half2float(h0), l1 = v.y - __half2float(h1);
    float l2 = v.z - __half2float(h2), l3 = v.w - __half2float(h3);
    __half2 hh0 = __halves2half2(h0, h1), hh1 = __halves2half2(h2, h3);
    *(uint2*)(phi + off) = make_uint2(*(uint32_t*)&hh0, *(uint32_t*)&hh1);
    *(uint2*)(plo + off) = make_uint2(pack_h2(l0, l1), pack_h2(l2, l3));
}

// exp2 on the FMA pipe (no MUFU); rel err ~2.4e-6.
__device__ __forceinline__ float fexp2(float x) {
    x = fmaxf(x, -28.f);
    float t = x + 12582912.f;
    float i = t - 12582912.f;
    float f = x - i;
    float p = 0.0013333558f;
    p = fmaf(p, f, 0.0096181291f);
    p = fmaf(p, f, 0.0555041087f);
    p = fmaf(p, f, 0.2402265069f);
    p = fmaf(p, f, 0.6931471806f);
    p = fmaf(p, f, 1.0f);
    int ei = (int)i;
    return p * __int_as_float((127 + ei) << 23);
}

// ===========================================================================
// Pre-split: fp32 -> bf16 hi/lo arrays (one pass).
// ===========================================================================
__global__ __launch_bounds__(256)
void split_f32(const float* __restrict__ src, __nv_bfloat16* __restrict__ hi,
               __nv_bfloat16* __restrict__ lo, int n4)
{
    int i = blockIdx.x * blockDim.x + threadIdx.x;
    if (i >= n4) return;
    float4 v = *(const float4*)(src + (size_t)i * 4);
    __nv_bfloat16 h0 = __float2bfloat16_rn(v.x);
    __nv_bfloat16 h1 = __float2bfloat16_rn(v.y);
    __nv_bfloat16 h2 = __float2bfloat16_rn(v.z);
    __nv_bfloat16 h3 = __float2bfloat16_rn(v.w);
    __nv_bfloat16 l0 = __float2bfloat16_rn(v.x - __bfloat162float(h0));
    __nv_bfloat16 l1 = __float2bfloat16_rn(v.y - __bfloat162float(h1));
    __nv_bfloat16 l2 = __float2bfloat16_rn(v.z - __bfloat162float(h2));
    __nv_bfloat16 l3 = __float2bfloat16_rn(v.w - __bfloat162float(h3));
    *(uint2*)(hi + (size_t)i * 4) = make_uint2(pack_bf2(h0, h1), pack_bf2(h2, h3));
    *(uint2*)(lo + (size_t)i * 4) = make_uint2(pack_bf2(l0, l1), pack_bf2(l2, l3));
}

// ===========================================================================
// Warp-MMA GEMM on PRE-SPLIT bf16 inputs: C = A @ B^T.
// A hi/lo: [4096,1024] bf16, B hi/lo: [1024,1024] bf16.  CTA tile 128x128,
// K chunks of 64, cp.async loads, 3-MMA hi/lo compute.  8 warps, occ 2.
// MODE 0: C fp32 row-major.  MODE 1: C fp32 in [B,H,T,D] permuted layout.
// ===========================================================================
#define GEMM_SMEM 65536

template<int MODE>
__global__ __launch_bounds__(256, 2)
void gemm_ps(const __nv_bfloat16* __restrict__ Ah,
             const __nv_bfloat16* __restrict__ Al,
             const __nv_bfloat16* __restrict__ Bh,
             const __nv_bfloat16* __restrict__ Bl,
             float* __restrict__ C)
{
    extern __shared__ __align__(1024) char smem[];
    const uint32_t uAh = smem_addr_u32(smem);
    const uint32_t uAl = uAh + 16384;
    const uint32_t uBh = uAh + 32768;
    const uint32_t uBl = uAh + 49152;

    const int tid  = threadIdx.x;
    const int bcol = blockIdx.x;
    const int brow = blockIdx.y;
    const int warp = tid >> 5;
    const int lane = tid & 31;

    const int m0w = (warp >> 1) * 32;
    const int n0w = (warp & 1) * 64;

    const int ltile   = lane >> 3;
    const int within  = lane & 7;
    const int rowoff  = ((ltile & 1) << 3) + within;
    const int chalf   = (ltile >> 1) << 4;
    const int xorkey  = within << 4;

    // per-thread copy coordinates (4 x 16B chunks per tile)
    const int crow[4] = { (tid + 0)   >> 3, (tid + 256) >> 3,
                          (tid + 512) >> 3, (tid + 768) >> 3 };
    const int ccol = (tid & 7) * 8;          // element col within 64-chunk
    uint32_t cdst[4];
    #pragma unroll
    for (int j = 0; j < 4; ++j)
        cdst[j] = SMEM_SWIZZLE_128B((uint32_t)(crow[j] * 128 + ccol * 2));

    const __nv_bfloat16* pAh = Ah + (size_t)(brow * 128) * DM + ccol;
    const __nv_bfloat16* pAl = Al + (size_t)(brow * 128) * DM + ccol;
    const __nv_bfloat16* pBh = Bh + (size_t)(bcol * 128) * DM + ccol;
    const __nv_bfloat16* pBl = Bl + (size_t)(bcol * 128) * DM + ccol;

    float acc[2][8][4];
    #pragma unroll
    for (int i = 0; i < 2; i++)
        #pragma unroll
        for (int j = 0; j < 8; j++)
            #pragma unroll
            for (int q = 0; q < 4; q++) acc[i][j][q] = 0.f;

    for (int s = 0; s < 16; ++s) {
        const size_t koff = (size_t)s * 64;
        #pragma unroll
        for (int j = 0; j < 4; ++j) {
            const size_t ro = (size_t)crow[j] * DM + koff;
            cp_async16(uAh + cdst[j], pAh + ro);
            cp_async16(uAl + cdst[j], pAl + ro);
            cp_async16(uBh + cdst[j], pBh + ro);
            cp_async16(uBl + cdst[j], pBl + ro);
        }
        CP_COMMIT();
        CP_WAIT0();
        __syncthreads();

        #pragma unroll
        for (int ks = 0; ks < 4; ++ks) {
            const uint32_t coff = (uint32_t)((ks * 32 + chalf) ^ xorkey);

            uint32_t ah[2][4], al[2][4];
            #pragma unroll
            for (int i = 0; i < 2; i++) {
                uint32_t ra = (uint32_t)((m0w + i * 16 + rowoff) * 128) + coff;
                ldmatrix_x4(ah[i][0], ah[i][1], ah[i][2], ah[i][3], uAh + ra);
                ldmatrix_x4(al[i][0], al[i][1], al[i][2], al[i][3], uAl + ra);
            }

            #pragma unroll
            for (int g = 0; g < 4; ++g) {
                uint32_t rb = (uint32_t)((n0w + g * 16 + rowoff) * 128) + coff;
                uint32_t bh[4], bl[4];
                ldmatrix_x4(bh[0], bh[1], bh[2], bh[3], uBh + rb);
                ldmatrix_x4(bl[0], bl[1], bl[2], bl[3], uBl + rb);
                #pragma unroll
                for (int jj = 0; jj < 2; ++jj) {
                    int j = g * 2 + jj;
                    #pragma unroll
                    for (int i = 0; i < 2; i++) {
                        mma_bf16(acc[i][j], ah[i], bh[jj], bh[2 + jj]);
                        mma_bf16(acc[i][j], ah[i], bl[jj], bl[2 + jj]);
                        mma_bf16(acc[i][j], al[i], bh[jj], bh[2 + jj]);
                    }
                }
            }
        }
        __syncthreads();
    }

    const int rfrag = lane >> 2;
    const int cfrag = (lane & 3) * 2;
    #pragma unroll
    for (int i = 0; i < 2; i++) {
        #pragma unroll
        for (int j = 0; j < 8; j++) {
            int m = brow * 128 + m0w + i * 16 + rfrag;
            int n = bcol * 128 + n0w + j * 8 + cfrag;
            float2 v0 = make_float2(acc[i][j][0], acc[i][j][1]);
            float2 v1 = make_float2(acc[i][j][2], acc[i][j][3]);
            if (MODE == 0) {
                *(float2*)(C + (size_t)m * DM + n)       = v0;
                *(float2*)(C + (size_t)(m + 8) * DM + n) = v1;
            } else {
                int h = n >> 6, d = n & 63;
                int b0 = m >> 11, t0 = m & 2047;
                *(float2*)(C + ((size_t)((b0 << 4) + h) * TT + t0) * HD + d) = v0;
                int m8 = m + 8;
                int b1 = m8 >> 11, t1 = m8 & 2047;
                *(float2*)(C + ((size_t)((b1 << 4) + h) * TT + t1) * HD + d) = v1;
            }
        }
    }
}

// ===========================================================================
// Tensor-core flash attention (R8 structure).  Epilogue now writes bf16
// hi/lo split directly (feeds the O-projection GEMM with pre-split A).
// ===========================================================================
#define FLASH_SMEM 57344   // Qh 16K | Ql 16K | Kh 8K | Kl 8K | Vh 8K

__global__ __launch_bounds__(256, 1)
void flash_mma(const float* __restrict__ gq, const float* __restrict__ gk,
               const float* __restrict__ gv,
               __nv_bfloat16* __restrict__ oh, __nv_bfloat16* __restrict__ ol)
{
    extern __shared__ __align__(1024) char smem[];
    char* sQh = smem;
    char* sQl = smem + 16384;
    char* sKh = smem + 32768;
    char* sKl = smem + 40960;
    char* sVh = smem + 49152;
    const uint32_t uQh = smem_addr_u32(sQh);
    const uint32_t uQl = uQh + 16384;
    const uint32_t uKh = uQh + 32768;
    const uint32_t uKl = uQh + 40960;
    const uint32_t uVh = uQh + 49152;

    const int qb  = (int)gridDim.x - 1 - blockIdx.x;
    const int h   = blockIdx.y;
    const int b   = blockIdx.z;
    const int tid = threadIdx.x;
    const int warp = tid >> 5;
    const int lane = tid & 31;

    const int m0w = warp * 16;
    const int ltile  = lane >> 3;
    const int within = lane & 7;
    const int rowoff = ((ltile & 1) << 3) + within;
    const int chalf  = (ltile >> 1) << 4;
    const int xorkey = within << 4;
    const int g  = lane >> 2;
    const int t2 = lane & 3;

    const size_t bh = (size_t)(b * NH + h) * TT;
    const float* qptr = gq + (bh + (size_t)qb * 128) * HD;
    const float QS = 0.125f * 1.4426950408889634f;

    #pragma unroll
    for (int it = 0; it < 8; ++it) {
        int idx = tid + it * 256;
        int r   = idx >> 4;
        int c4  = (idx & 15) << 2;
        float4 v = *(const float4*)(qptr + (size_t)r * HD + c4);
        v.x *= QS; v.y *= QS; v.z *= QS; v.w *= QS;
        uint32_t off = SMEM_SWIZZLE_128B((uint32_t)(r * 128 + c4 * 2));
        split_store_h(sQh, sQl, off, v);
    }
    __syncthreads();

    uint32_t qh[4][4], ql[4][4];
    #pragma unroll
    for (int ks = 0; ks < 4; ++ks) {
        uint32_t coff = (uint32_t)((ks * 32 + chalf) ^ xorkey);
        uint32_t ra = (uint32_t)((m0w + rowoff) * 128) + coff;
        ldmatrix_x4(qh[ks][0], qh[ks][1], qh[ks][2], qh[ks][3], uQh + ra);
        ldmatrix_x4(ql[ks][0], ql[ks][1], ql[ks][2], ql[ks][3], uQl + ra);
    }

    float o[8][4];
    #pragma unroll
    for (int j = 0; j < 8; j++)
        #pragma unroll
        for (int q = 0; q < 4; q++) o[j][q] = 0.f;
    float m0 = -100000.f, m1 = -100000.f, l0 = 0.f, l1 = 0.f;

    const int r0g = qb * 128 + m0w + g;
    const int r1g = r0g + 8;
    const int jb_max = 2 * qb + 1;

    for (int jb = 0; jb <= jb_max; ++jb) {
        const float* kptr = gk + (bh + (size_t)jb * 64) * HD;
        const float* vptr = gv + (bh + (size_t)jb * 64) * HD;
        __syncthreads();
        #pragma unroll
        for (int it = 0; it < 4; ++it) {
            int idx = tid + it * 256;
            int r   = idx >> 4;
            int c4  = (idx & 15) << 2;
            uint32_t off = SMEM_SWIZZLE_128B((uint32_t)(r * 128 + c4 * 2));
            float4 kv = *(const float4*)(kptr + (size_t)r * HD + c4);
            split_store_h(sKh, sKl, off, kv);
            float4 vv = *(const float4*)(vptr + (size_t)r * HD + c4);
            *(uint2*)(sVh + off) = make_uint2(pack_h2(vv.x, vv.y),
                                              pack_h2(vv.z, vv.w));
        }
        __syncthreads();

        float acc[8][4];
        #pragma unroll
        for (int j = 0; j < 8; j++)
            #pragma unroll
            for (int q = 0; q < 4; q++) acc[j][q] = 0.f;

        #pragma unroll
        for (int ks = 0; ks < 4; ++ks) {
            uint32_t coff = (uint32_t)((ks * 32 + chalf) ^ xorkey);
            #pragma unroll
            for (int g4 = 0; g4 < 4; ++g4) {
                uint32_t rb = (uint32_t)((g4 * 16 + rowoff) * 128) + coff;
                uint32_t kh[4], kl[4];
                ldmatrix_x4(kh[0], kh[1], kh[2], kh[3], uKh + rb);
                ldmatrix_x4(kl[0], kl[1], kl[2], kl[3], uKl + rb);
                #pragma unroll
                for (int jj = 0; jj < 2; ++jj) {
                    int j = g4 * 2 + jj;
                    mma_f16(acc[j], qh[ks], kh[jj], kh[2 + jj]);
                    mma_f16(acc[j], qh[ks], kl[jj], kl[2 + jj]);
                    mma_f16(acc[j], ql[ks], kh[jj], kh[2 + jj]);
                }
            }
        }

        if (jb >= 2 * qb) {
            #pragma unroll
            for (int j = 0; j < 8; j++) {
                int cb = jb * 64 + j * 8 + t2 * 2;
                if (cb     > r0g) acc[j][0] = -30000.f;
                if (cb + 1 > r0g) acc[j][1] = -30000.f;
                if (cb     > r1g) acc[j][2] = -30000.f;
                if (cb + 1 > r1g) acc[j][3] = -30000.f;
            }
        }

        float mx0 = -30000.f, mx1 = -30000.f;
        #pragma unroll
        for (int j = 0; j < 8; j++) {
            mx0 = fmaxf(mx0, fmaxf(acc[j][0], acc[j][1]));
            mx1 = fmaxf(mx1, fmaxf(acc[j][2], acc[j][3]));
        }
        mx0 = fmaxf(mx0, __shfl_xor_sync(0xffffffffu, mx0, 1));
        mx0 = fmaxf(mx0, __shfl_xor_sync(0xffffffffu, mx0, 2));
        mx1 = fmaxf(mx1, __shfl_xor_sync(0xffffffffu, mx1, 1));
        mx1 = fmaxf(mx1, __shfl_xor_sync(0xffffffffu, mx1, 2));

        float mn0 = fmaxf(m0, mx0), mn1 = fmaxf(m1, mx1);
        float a0 = fexp2(m0 - mn0), a1 = fexp2(m1 - mn1);
        m0 = mn0; m1 = mn1;

        float rs0 = 0.f, rs1 = 0.f;
        #pragma unroll
        for (int j = 0; j < 8; j++) {
            acc[j][0] = fexp2(acc[j][0] - mn0);
            acc[j][1] = fexp2(acc[j][1] - mn0);
            acc[j][2] = fexp2(acc[j][2] - mn1);
            acc[j][3] = fexp2(acc[j][3] - mn1);
            rs0 += acc[j][0] + acc[j][1];
            rs1 += acc[j][2] + acc[j][3];
        }
        rs0 += __shfl_xor_sync(0xffffffffu, rs0, 1);
        rs0 += __shfl_xor_sync(0xffffffffu, rs0, 2);
        rs1 += __shfl_xor_sync(0xffffffffu, rs1, 1);
        rs1 += __shfl_xor_sync(0xffffffffu, rs1, 2);
        l0 = l0 * a0 + rs0;
        l1 = l1 * a1 + rs1;

        #pragma unroll
        for (int j = 0; j < 8; j++) {
            o[j][0] *= a0; o[j][1] *= a0;
            o[j][2] *= a1; o[j][3] *= a1;
        }

        uint32_t pf[4][4];
        #pragma unroll
        for (int j0 = 0; j0 < 4; ++j0) {
            pf[j0][0] = pack_h2(acc[2*j0][0],   acc[2*j0][1]);
            pf[j0][1] = pack_h2(acc[2*j0][2],   acc[2*j0][3]);
            pf[j0][2] = pack_h2(acc[2*j0+1][0], acc[2*j0+1][1]);
            pf[j0][3] = pack_h2(acc[2*j0+1][2], acc[2*j0+1][3]);
        }

        #pragma unroll
        for (int s0t = 0; s0t < 4; ++s0t) {
            #pragma unroll
            for (int d0t = 0; d0t < 4; ++d0t) {
                uint32_t addr = uVh + (uint32_t)((s0t * 16 + rowoff) * 128)
                              + (uint32_t)((d0t * 32 + chalf) ^ xorkey);
                uint32_t w0, w1, w2, w3;
                ldmatrix_x4_trans(w0, w1, w2, w3, addr);
                mma_f16(o[d0t * 2],     pf[s0t], w0, w1);
                mma_f16(o[d0t * 2 + 1], pf[s0t], w2, w3);
            }
        }
    }

    // ---- epilogue: O /= l, write bf16 hi/lo split in [B,T,H*D] ----
    float inv0 = 1.f / l0, inv1 = 1.f / l1;
    const int tg0 = qb * 128 + m0w + g;
    const int tg1 = tg0 + 8;
    #pragma unroll
    for (int j = 0; j < 8; j++) {
        int d = h * HD + j * 8 + t2 * 2;
        size_t off0 = (size_t)(b * TT + tg0) * DM + d;
        size_t off1 = (size_t)(b * TT + tg1) * DM + d;
        float v00 = o[j][0] * inv0, v01 = o[j][1] * inv0;
        float v10 = o[j][2] * inv1, v11 = o[j][3] * inv1;
        __nv_bfloat16 h00 = __float2bfloat16_rn(v00);
        __nv_bfloat16 h01 = __float2bfloat16_rn(v01);
        __nv_bfloat16 h10 = __float2bfloat16_rn(v10);
        __nv_bfloat16 h11 = __float2bfloat16_rn(v11);
        *(uint32_t*)(oh + off0) = pack_bf2(h00, h01);
        *(uint32_t*)(oh + off1) = pack_bf2(h10, h11);
        *(uint32_t*)(ol + off0) = pack_bf2(
            __float2bfloat16_rn(v00 - __bfloat162float(h00)),
            __float2bfloat16_rn(v01 - __bfloat162float(h01)));
        *(uint32_t*)(ol + off1) = pack_bf2(
            __float2bfloat16_rn(v10 - __bfloat162float(h10)),
            __float2bfloat16_rn(v11 - __bfloat162float(h11)));
    }
}

// ---------------------------------------------------------------------------
extern "C" void kernel_launch(void* const* d_in, const int* in_sizes, int n_in,
                              void* d_out, int out_size)
{
    const float* x  = (const float*)d_in[0];
    const float* Wq = (const float*)d_in[1];
    const float* Wk = (const float*)d_in[2];
    const float* Wv = (const float*)d_in[3];
    const float* Wo = (const float*)d_in[4];
    float* out = (float*)d_out;

    float *gq, *gk, *gv;
    __nv_bfloat16 *xh, *xl, *wh, *wl, *ah, *al;
    cudaGetSymbolAddress((void**)&gq, g_q);
    cudaGetSymbolAddress((void**)&gk, g_k);
    cudaGetSymbolAddress((void**)&gv, g_v);
    cudaGetSymbolAddress((void**)&xh, g_xh);
    cudaGetSymbolAddress((void**)&xl, g_xl);
    cudaGetSymbolAddress((void**)&wh, g_wh);
    cudaGetSymbolAddress((void**)&wl, g_wl);
    cudaGetSymbolAddress((void**)&ah, g_ah);
    cudaGetSymbolAddress((void**)&al, g_al);

    cudaFuncSetAttribute(gemm_ps<0>, cudaFuncAttributeMaxDynamicSharedMemorySize, GEMM_SMEM);
    cudaFuncSetAttribute(gemm_ps<1>, cudaFuncAttributeMaxDynamicSharedMemorySize, GEMM_SMEM);
    cudaFuncSetAttribute(flash_mma,  cudaFuncAttributeMaxDynamicSharedMemorySize, FLASH_SMEM);

    // pre-split x and weights to bf16 hi/lo (once)
    split_f32<<<(MM * DM / 4 + 255) / 256, 256>>>(x,  xh, xl, MM * DM / 4);
    split_f32<<<(int)(WSZ / 4 + 255) / 256, 256>>>(Wq, wh,           wl,           (int)(WSZ / 4));
    split_f32<<<(int)(WSZ / 4 + 255) / 256, 256>>>(Wk, wh + WSZ,     wl + WSZ,     (int)(WSZ / 4));
    split_f32<<<(int)(WSZ / 4 + 255) / 256, 256>>>(Wv, wh + 2 * WSZ, wl + 2 * WSZ, (int)(WSZ / 4));
    split_f32<<<(int)(WSZ / 4 + 255) / 256, 256>>>(Wo, wh + 3 * WSZ, wl + 3 * WSZ, (int)(WSZ / 4));

    dim3 gemm_grid(DM / 128, MM / 128);   // (8, 32)
    gemm_ps<1><<<gemm_grid, 256, GEMM_SMEM>>>(xh, xl, wh,           wl,           gq);
    gemm_ps<1><<<gemm_grid, 256, GEMM_SMEM>>>(xh, xl, wh + WSZ,     wl + WSZ,     gk);
    gemm_ps<1><<<gemm_grid, 256, GEMM_SMEM>>>(xh, xl, wh + 2 * WSZ, wl + 2 * WSZ, gv);

    flash_mma<<<dim3(TT / 128, NH, BB), 256, FLASH_SMEM>>>(gq, gk, gv, ah, al);

    gemm_ps<0><<<gemm_grid, 256, GEMM_SMEM>>>(ah, al, wh + 3 * WSZ, wl + 3 * WSZ, out);
}

// round 10
// speedup vs baseline: 1.5282x; 1.5282x over previous
#include <cuda_runtime.h>
#include <cuda_bf16.h>
#include <cuda_fp16.h>
#include <cstdint>

#define DM 1024
#define NH 16
#define HD 64
#define BB 2
#define TT 2048
#define MM (BB*TT)   // 4096 rows
#define WSZ ((size_t)DM * DM)

// Scratch. Q,K,V fp32 in [B,H,T,D]; x & weights & attn-out pre-split bf16 hi/lo.
__device__ float g_q[(size_t)MM * DM];
__device__ float g_k[(size_t)MM * DM];
__device__ float g_v[(size_t)MM * DM];
__device__ __nv_bfloat16 g_xh[(size_t)MM * DM];
__device__ __nv_bfloat16 g_xl[(size_t)MM * DM];
__device__ __nv_bfloat16 g_wh[4 * WSZ];
__device__ __nv_bfloat16 g_wl[4 * WSZ];
__device__ __nv_bfloat16 g_ah[(size_t)MM * DM];
__device__ __nv_bfloat16 g_al[(size_t)MM * DM];

__device__ __forceinline__ uint32_t smem_addr_u32(const void* smem_ptr) {
    uint32_t addr;
    asm("{ .reg .u64 tmp; cvta.to.shared.u64 tmp, %1; cvt.u32.u64 %0, tmp; }"
        : "=r"(addr) : "l"(smem_ptr));
    return addr;
}

#define SMEM_SWIZZLE_128B(byte_offset) \
    ((byte_offset) ^ (((byte_offset) >> 3) & 0x70))

__device__ __forceinline__ void cp_async16(uint32_t dst, const void* src) {
    asm volatile("cp.async.cg.shared.global [%0], [%1], 16;"
                 :: "r"(dst), "l"(src));
}
#define CP_COMMIT() asm volatile("cp.async.commit_group;" ::: "memory")

__device__ __forceinline__ void ldmatrix_x4(uint32_t& r0, uint32_t& r1,
                                            uint32_t& r2, uint32_t& r3,
                                            uint32_t addr) {
    asm volatile("ldmatrix.sync.aligned.m8n8.x4.shared.b16 {%0,%1,%2,%3}, [%4];"
                 : "=r"(r0), "=r"(r1), "=r"(r2), "=r"(r3) : "r"(addr));
}

__device__ __forceinline__ void ldmatrix_x4_trans(uint32_t& r0, uint32_t& r1,
                                                  uint32_t& r2, uint32_t& r3,
                                                  uint32_t addr) {
    asm volatile("ldmatrix.sync.aligned.m8n8.x4.trans.shared.b16 {%0,%1,%2,%3}, [%4];"
                 : "=r"(r0), "=r"(r1), "=r"(r2), "=r"(r3) : "r"(addr));
}

__device__ __forceinline__ void mma_bf16(float* d, const uint32_t* a,
                                         uint32_t b0, uint32_t b1) {
    asm volatile(
        "mma.sync.aligned.m16n8k16.row.col.f32.bf16.bf16.f32 "
        "{%0,%1,%2,%3}, {%4,%5,%6,%7}, {%8,%9}, {%0,%1,%2,%3};"
        : "+f"(d[0]), "+f"(d[1]), "+f"(d[2]), "+f"(d[3])
        : "r"(a[0]), "r"(a[1]), "r"(a[2]), "r"(a[3]), "r"(b0), "r"(b1));
}

__device__ __forceinline__ void mma_f16(float* d, const uint32_t* a,
                                        uint32_t b0, uint32_t b1) {
    asm volatile(
        "mma.sync.aligned.m16n8k16.row.col.f32.f16.f16.f32 "
        "{%0,%1,%2,%3}, {%4,%5,%6,%7}, {%8,%9}, {%0,%1,%2,%3};"
        : "+f"(d[0]), "+f"(d[1]), "+f"(d[2]), "+f"(d[3])
        : "r"(a[0]), "r"(a[1]), "r"(a[2]), "r"(a[3]), "r"(b0), "r"(b1));
}

__device__ __forceinline__ uint32_t pack_bf2(__nv_bfloat16 a, __nv_bfloat16 b) {
    return ((uint32_t)__bfloat16_as_ushort(b) << 16) | (uint32_t)__bfloat16_as_ushort(a);
}

__device__ __forceinline__ uint32_t pack_h2(float a, float b) {
    __half2 h = __floats2half2_rn(a, b);
    return *(uint32_t*)&h;
}

// fp32 -> fp16 hi/lo split (flash path)
__device__ __forceinline__ void split_store_h(char* phi, char* plo, uint32_t off,
                                              float4 v) {
    __half h0 = __float2half_rn(v.x), h1 = __float2half_rn(v.y);
    __half h2 = __float2half_rn(v.z), h3 = __float2half_rn(v.w);
    float l0 = v.x - __half2float(h0), l1 = v.y - __half2float(h1);
    float l2 = v.z - __half2float(h2), l3 = v.w - __half2float(h3);
    __half2 hh0 = __halves2half2(h0, h1), hh1 = __halves2half2(h2, h3);
    *(uint2*)(phi + off) = make_uint2(*(uint32_t*)&hh0, *(uint32_t*)&hh1);
    *(uint2*)(plo + off) = make_uint2(pack_h2(l0, l1), pack_h2(l2, l3));
}

// exp2 on the FMA pipe (no MUFU); rel err ~2.4e-6.
__device__ __forceinline__ float fexp2(float x) {
    x = fmaxf(x, -28.f);
    float t = x + 12582912.f;
    float i = t - 12582912.f;
    float f = x - i;
    float p = 0.0013333558f;
    p = fmaf(p, f, 0.0096181291f);
    p = fmaf(p, f, 0.0555041087f);
    p = fmaf(p, f, 0.2402265069f);
    p = fmaf(p, f, 0.6931471806f);
    p = fmaf(p, f, 1.0f);
    int ei = (int)i;
    return p * __int_as_float((127 + ei) << 23);
}

// ===========================================================================
// Pre-split: fp32 -> bf16 hi/lo arrays (one pass).
// ===========================================================================
__global__ __launch_bounds__(256)
void split_f32(const float* __restrict__ src, __nv_bfloat16* __restrict__ hi,
               __nv_bfloat16* __restrict__ lo, int n4)
{
    int i = blockIdx.x * blockDim.x + threadIdx.x;
    if (i >= n4) return;
    float4 v = *(const float4*)(src + (size_t)i * 4);
    __nv_bfloat16 h0 = __float2bfloat16_rn(v.x);
    __nv_bfloat16 h1 = __float2bfloat16_rn(v.y);
    __nv_bfloat16 h2 = __float2bfloat16_rn(v.z);
    __nv_bfloat16 h3 = __float2bfloat16_rn(v.w);
    __nv_bfloat16 l0 = __float2bfloat16_rn(v.x - __bfloat162float(h0));
    __nv_bfloat16 l1 = __float2bfloat16_rn(v.y - __bfloat162float(h1));
    __nv_bfloat16 l2 = __float2bfloat16_rn(v.z - __bfloat162float(h2));
    __nv_bfloat16 l3 = __float2bfloat16_rn(v.w - __bfloat162float(h3));
    *(uint2*)(hi + (size_t)i * 4) = make_uint2(pack_bf2(h0, h1), pack_bf2(h2, h3));
    *(uint2*)(lo + (size_t)i * 4) = make_uint2(pack_bf2(l0, l1), pack_bf2(l2, l3));
}

// Fused splitter for the 4 weight matrices (one launch).
__global__ __launch_bounds__(256)
void split_w4(const float* __restrict__ w0, const float* __restrict__ w1,
              const float* __restrict__ w2, const float* __restrict__ w3,
              __nv_bfloat16* __restrict__ hi, __nv_bfloat16* __restrict__ lo)
{
    const int n4 = (int)(WSZ / 4);
    int i = blockIdx.x * blockDim.x + threadIdx.x;
    int which = i / n4;
    int idx = i - which * n4;
    const float* src = (which == 0) ? w0 : (which == 1) ? w1
                     : (which == 2) ? w2 : w3;
    float4 v = *(const float4*)(src + (size_t)idx * 4);
    size_t o = (size_t)which * WSZ + (size_t)idx * 4;
    __nv_bfloat16 h0 = __float2bfloat16_rn(v.x);
    __nv_bfloat16 h1 = __float2bfloat16_rn(v.y);
    __nv_bfloat16 h2 = __float2bfloat16_rn(v.z);
    __nv_bfloat16 h3 = __float2bfloat16_rn(v.w);
    __nv_bfloat16 l0 = __float2bfloat16_rn(v.x - __bfloat162float(h0));
    __nv_bfloat16 l1 = __float2bfloat16_rn(v.y - __bfloat162float(h1));
    __nv_bfloat16 l2 = __float2bfloat16_rn(v.z - __bfloat162float(h2));
    __nv_bfloat16 l3 = __float2bfloat16_rn(v.w - __bfloat162float(h3));
    *(uint2*)(hi + o) = make_uint2(pack_bf2(h0, h1), pack_bf2(h2, h3));
    *(uint2*)(lo + o) = make_uint2(pack_bf2(l0, l1), pack_bf2(l2, l3));
}

// ===========================================================================
// Warp-MMA GEMM on PRE-SPLIT bf16, double-buffered cp.async pipeline.
// C = A @ B^T.  CTA tile 128x128, K chunks of 64, 3-MMA hi/lo compute.
// Smem: 2 stage buffers x 64KB = 128KB (occ 1; pipeline hides latency).
// MODE 0: C fp32 row-major.  MODE 1: C fp32 in [B,H,T,D] permuted layout.
// ===========================================================================
#define STG 65536
#define GEMM_SMEM (2 * STG)

template<int MODE>
__global__ __launch_bounds__(256, 1)
void gemm_ps(const __nv_bfloat16* __restrict__ Ah,
             const __nv_bfloat16* __restrict__ Al,
             const __nv_bfloat16* __restrict__ Bh,
             const __nv_bfloat16* __restrict__ Bl,
             float* __restrict__ C)
{
    extern __shared__ __align__(1024) char smem[];
    const uint32_t sb = smem_addr_u32(smem);

    const int tid  = threadIdx.x;
    const int bcol = blockIdx.x;
    const int brow = blockIdx.y;
    const int warp = tid >> 5;
    const int lane = tid & 31;

    const int m0w = (warp >> 1) * 32;
    const int n0w = (warp & 1) * 64;

    const int ltile   = lane >> 3;
    const int within  = lane & 7;
    const int rowoff  = ((ltile & 1) << 3) + within;
    const int chalf   = (ltile >> 1) << 4;
    const int xorkey  = within << 4;

    // per-thread copy coordinates (4 x 16B chunks per 128x64 tile)
    const int crow[4] = { (tid + 0)   >> 3, (tid + 256) >> 3,
                          (tid + 512) >> 3, (tid + 768) >> 3 };
    const int ccol = (tid & 7) * 8;
    uint32_t cdst[4];
    #pragma unroll
    for (int j = 0; j < 4; ++j)
        cdst[j] = SMEM_SWIZZLE_128B((uint32_t)(crow[j] * 128 + ccol * 2));

    const __nv_bfloat16* pAh = Ah + (size_t)(brow * 128) * DM + ccol;
    const __nv_bfloat16* pAl = Al + (size_t)(brow * 128) * DM + ccol;
    const __nv_bfloat16* pBh = Bh + (size_t)(bcol * 128) * DM + ccol;
    const __nv_bfloat16* pBl = Bl + (size_t)(bcol * 128) * DM + ccol;

    // issue one stage's 16 cp.async (4 chunks x {Ah,Al,Bh,Bl})
    auto prefetch = [&](int s) {
        const uint32_t b0 = sb + (uint32_t)(s & 1) * STG;
        const size_t koff = (size_t)s * 64;
        #pragma unroll
        for (int j = 0; j < 4; ++j) {
            const size_t ro = (size_t)crow[j] * DM + koff;
            cp_async16(b0 +         cdst[j], pAh + ro);
            cp_async16(b0 + 16384 + cdst[j], pAl + ro);
            cp_async16(b0 + 32768 + cdst[j], pBh + ro);
            cp_async16(b0 + 49152 + cdst[j], pBl + ro);
        }
        CP_COMMIT();
    };

    float acc[2][8][4];
    #pragma unroll
    for (int i = 0; i < 2; i++)
        #pragma unroll
        for (int j = 0; j < 8; j++)
            #pragma unroll
            for (int q = 0; q < 4; q++) acc[i][j][q] = 0.f;

    prefetch(0);

    for (int s = 0; s < 16; ++s) {
        if (s + 1 < 16) {
            prefetch(s + 1);
            asm volatile("cp.async.wait_group 1;" ::: "memory");
        } else {
            asm volatile("cp.async.wait_group 0;" ::: "memory");
        }
        __syncthreads();

        const uint32_t uAh = sb + (uint32_t)(s & 1) * STG;
        const uint32_t uAl = uAh + 16384;
        const uint32_t uBh = uAh + 32768;
        const uint32_t uBl = uAh + 49152;

        #pragma unroll
        for (int ks = 0; ks < 4; ++ks) {
            const uint32_t coff = (uint32_t)((ks * 32 + chalf) ^ xorkey);

            uint32_t ah[2][4], al[2][4];
            #pragma unroll
            for (int i = 0; i < 2; i++) {
                uint32_t ra = (uint32_t)((m0w + i * 16 + rowoff) * 128) + coff;
                ldmatrix_x4(ah[i][0], ah[i][1], ah[i][2], ah[i][3], uAh + ra);
                ldmatrix_x4(al[i][0], al[i][1], al[i][2], al[i][3], uAl + ra);
            }

            #pragma unroll
            for (int g = 0; g < 4; ++g) {
                uint32_t rb = (uint32_t)((n0w + g * 16 + rowoff) * 128) + coff;
                uint32_t bh[4], bl[4];
                ldmatrix_x4(bh[0], bh[1], bh[2], bh[3], uBh + rb);
                ldmatrix_x4(bl[0], bl[1], bl[2], bl[3], uBl + rb);
                #pragma unroll
                for (int jj = 0; jj < 2; ++jj) {
                    int j = g * 2 + jj;
                    #pragma unroll
                    for (int i = 0; i < 2; i++) {
                        mma_bf16(acc[i][j], ah[i], bh[jj], bh[2 + jj]);
                        mma_bf16(acc[i][j], ah[i], bl[jj], bl[2 + jj]);
                        mma_bf16(acc[i][j], al[i], bh[jj], bh[2 + jj]);
                    }
                }
            }
        }
        __syncthreads();   // stage buffer free for prefetch(s+2)
    }

    const int rfrag = lane >> 2;
    const int cfrag = (lane & 3) * 2;
    #pragma unroll
    for (int i = 0; i < 2; i++) {
        #pragma unroll
        for (int j = 0; j < 8; j++) {
            int m = brow * 128 + m0w + i * 16 + rfrag;
            int n = bcol * 128 + n0w + j * 8 + cfrag;
            float2 v0 = make_float2(acc[i][j][0], acc[i][j][1]);
            float2 v1 = make_float2(acc[i][j][2], acc[i][j][3]);
            if (MODE == 0) {
                *(float2*)(C + (size_t)m * DM + n)       = v0;
                *(float2*)(C + (size_t)(m + 8) * DM + n) = v1;
            } else {
                int h = n >> 6, d = n & 63;
                int b0 = m >> 11, t0 = m & 2047;
                *(float2*)(C + ((size_t)((b0 << 4) + h) * TT + t0) * HD + d) = v0;
                int m8 = m + 8;
                int b1 = m8 >> 11, t1 = m8 & 2047;
                *(float2*)(C + ((size_t)((b1 << 4) + h) * TT + t1) * HD + d) = v1;
            }
        }
    }
}

// ===========================================================================
// Tensor-core flash attention (R8 structure, bf16 hi/lo output epilogue).
// ===========================================================================
#define FLASH_SMEM 57344   // Qh 16K | Ql 16K | Kh 8K | Kl 8K | Vh 8K

__global__ __launch_bounds__(256, 1)
void flash_mma(const float* __restrict__ gq, const float* __restrict__ gk,
               const float* __restrict__ gv,
               __nv_bfloat16* __restrict__ oh, __nv_bfloat16* __restrict__ ol)
{
    extern __shared__ __align__(1024) char smem[];
    char* sQh = smem;
    char* sQl = smem + 16384;
    char* sKh = smem + 32768;
    char* sKl = smem + 40960;
    char* sVh = smem + 49152;
    const uint32_t uQh = smem_addr_u32(sQh);
    const uint32_t uQl = uQh + 16384;
    const uint32_t uKh = uQh + 32768;
    const uint32_t uKl = uQh + 40960;
    const uint32_t uVh = uQh + 49152;

    const int qb  = (int)gridDim.x - 1 - blockIdx.x;
    const int h   = blockIdx.y;
    const int b   = blockIdx.z;
    const int tid = threadIdx.x;
    const int warp = tid >> 5;
    const int lane = tid & 31;

    const int m0w = warp * 16;
    const int ltile  = lane >> 3;
    const int within = lane & 7;
    const int rowoff = ((ltile & 1) << 3) + within;
    const int chalf  = (ltile >> 1) << 4;
    const int xorkey = within << 4;
    const int g  = lane >> 2;
    const int t2 = lane & 3;

    const size_t bh = (size_t)(b * NH + h) * TT;
    const float* qptr = gq + (bh + (size_t)qb * 128) * HD;
    const float QS = 0.125f * 1.4426950408889634f;

    #pragma unroll
    for (int it = 0; it < 8; ++it) {
        int idx = tid + it * 256;
        int r   = idx >> 4;
        int c4  = (idx & 15) << 2;
        float4 v = *(const float4*)(qptr + (size_t)r * HD + c4);
        v.x *= QS; v.y *= QS; v.z *= QS; v.w *= QS;
        uint32_t off = SMEM_SWIZZLE_128B((uint32_t)(r * 128 + c4 * 2));
        split_store_h(sQh, sQl, off, v);
    }
    __syncthreads();

    uint32_t qh[4][4], ql[4][4];
    #pragma unroll
    for (int ks = 0; ks < 4; ++ks) {
        uint32_t coff = (uint32_t)((ks * 32 + chalf) ^ xorkey);
        uint32_t ra = (uint32_t)((m0w + rowoff) * 128) + coff;
        ldmatrix_x4(qh[ks][0], qh[ks][1], qh[ks][2], qh[ks][3], uQh + ra);
        ldmatrix_x4(ql[ks][0], ql[ks][1], ql[ks][2], ql[ks][3], uQl + ra);
    }

    float o[8][4];
    #pragma unroll
    for (int j = 0; j < 8; j++)
        #pragma unroll
        for (int q = 0; q < 4; q++) o[j][q] = 0.f;
    float m0 = -100000.f, m1 = -100000.f, l0 = 0.f, l1 = 0.f;

    const int r0g = qb * 128 + m0w + g;
    const int r1g = r0g + 8;
    const int jb_max = 2 * qb + 1;

    for (int jb = 0; jb <= jb_max; ++jb) {
        const float* kptr = gk + (bh + (size_t)jb * 64) * HD;
        const float* vptr = gv + (bh + (size_t)jb * 64) * HD;
        __syncthreads();
        #pragma unroll
        for (int it = 0; it < 4; ++it) {
            int idx = tid + it * 256;
            int r   = idx >> 4;
            int c4  = (idx & 15) << 2;
            uint32_t off = SMEM_SWIZZLE_128B((uint32_t)(r * 128 + c4 * 2));
            float4 kv = *(const float4*)(kptr + (size_t)r * HD + c4);
            split_store_h(sKh, sKl, off, kv);
            float4 vv = *(const float4*)(vptr + (size_t)r * HD + c4);
            *(uint2*)(sVh + off) = make_uint2(pack_h2(vv.x, vv.y),
                                              pack_h2(vv.z, vv.w));
        }
        __syncthreads();

        float acc[8][4];
        #pragma unroll
        for (int j = 0; j < 8; j++)
            #pragma unroll
            for (int q = 0; q < 4; q++) acc[j][q] = 0.f;

        #pragma unroll
        for (int ks = 0; ks < 4; ++ks) {
            uint32_t coff = (uint32_t)((ks * 32 + chalf) ^ xorkey);
            #pragma unroll
            for (int g4 = 0; g4 < 4; ++g4) {
                uint32_t rb = (uint32_t)((g4 * 16 + rowoff) * 128) + coff;
                uint32_t kh[4], kl[4];
                ldmatrix_x4(kh[0], kh[1], kh[2], kh[3], uKh + rb);
                ldmatrix_x4(kl[0], kl[1], kl[2], kl[3], uKl + rb);
                #pragma unroll
                for (int jj = 0; jj < 2; ++jj) {
                    int j = g4 * 2 + jj;
                    mma_f16(acc[j], qh[ks], kh[jj], kh[2 + jj]);
                    mma_f16(acc[j], qh[ks], kl[jj], kl[2 + jj]);
                    mma_f16(acc[j], ql[ks], kh[jj], kh[2 + jj]);
                }
            }
        }

        if (jb >= 2 * qb) {
            #pragma unroll
            for (int j = 0; j < 8; j++) {
                int cb = jb * 64 + j * 8 + t2 * 2;
                if (cb     > r0g) acc[j][0] = -30000.f;
                if (cb + 1 > r0g) acc[j][1] = -30000.f;
                if (cb     > r1g) acc[j][2] = -30000.f;
                if (cb + 1 > r1g) acc[j][3] = -30000.f;
            }
        }

        float mx0 = -30000.f, mx1 = -30000.f;
        #pragma unroll
        for (int j = 0; j < 8; j++) {
            mx0 = fmaxf(mx0, fmaxf(acc[j][0], acc[j][1]));
            mx1 = fmaxf(mx1, fmaxf(acc[j][2], acc[j][3]));
        }
        mx0 = fmaxf(mx0, __shfl_xor_sync(0xffffffffu, mx0, 1));
        mx0 = fmaxf(mx0, __shfl_xor_sync(0xffffffffu, mx0, 2));
        mx1 = fmaxf(mx1, __shfl_xor_sync(0xffffffffu, mx1, 1));
        mx1 = fmaxf(mx1, __shfl_xor_sync(0xffffffffu, mx1, 2));

        float mn0 = fmaxf(m0, mx0), mn1 = fmaxf(m1, mx1);
        float a0 = fexp2(m0 - mn0), a1 = fexp2(m1 - mn1);
        m0 = mn0; m1 = mn1;

        float rs0 = 0.f, rs1 = 0.f;
        #pragma unroll
        for (int j = 0; j < 8; j++) {
            acc[j][0] = fexp2(acc[j][0] - mn0);
            acc[j][1] = fexp2(acc[j][1] - mn0);
            acc[j][2] = fexp2(acc[j][2] - mn1);
            acc[j][3] = fexp2(acc[j][3] - mn1);
            rs0 += acc[j][0] + acc[j][1];
            rs1 += acc[j][2] + acc[j][3];
        }
        rs0 += __shfl_xor_sync(0xffffffffu, rs0, 1);
        rs0 += __shfl_xor_sync(0xffffffffu, rs0, 2);
        rs1 += __shfl_xor_sync(0xffffffffu, rs1, 1);
        rs1 += __shfl_xor_sync(0xffffffffu, rs1, 2);
        l0 = l0 * a0 + rs0;
        l1 = l1 * a1 + rs1;

        #pragma unroll
        for (int j = 0; j < 8; j++) {
            o[j][0] *= a0; o[j][1] *= a0;
            o[j][2] *= a1; o[j][3] *= a1;
        }

        uint32_t pf[4][4];
        #pragma unroll
        for (int j0 = 0; j0 < 4; ++j0) {
            pf[j0][0] = pack_h2(acc[2*j0][0],   acc[2*j0][1]);
            pf[j0][1] = pack_h2(acc[2*j0][2],   acc[2*j0][3]);
            pf[j0][2] = pack_h2(acc[2*j0+1][0], acc[2*j0+1][1]);
            pf[j0][3] = pack_h2(acc[2*j0+1][2], acc[2*j0+1][3]);
        }

        #pragma unroll
        for (int s0t = 0; s0t < 4; ++s0t) {
            #pragma unroll
            for (int d0t = 0; d0t < 4; ++d0t) {
                uint32_t addr = uVh + (uint32_t)((s0t * 16 + rowoff) * 128)
                              + (uint32_t)((d0t * 32 + chalf) ^ xorkey);
                uint32_t w0, w1, w2, w3;
                ldmatrix_x4_trans(w0, w1, w2, w3, addr);
                mma_f16(o[d0t * 2],     pf[s0t], w0, w1);
                mma_f16(o[d0t * 2 + 1], pf[s0t], w2, w3);
            }
        }
    }

    float inv0 = 1.f / l0, inv1 = 1.f / l1;
    const int tg0 = qb * 128 + m0w + g;
    const int tg1 = tg0 + 8;
    #pragma unroll
    for (int j = 0; j < 8; j++) {
        int d = h * HD + j * 8 + t2 * 2;
        size_t off0 = (size_t)(b * TT + tg0) * DM + d;
        size_t off1 = (size_t)(b * TT + tg1) * DM + d;
        float v00 = o[j][0] * inv0, v01 = o[j][1] * inv0;
        float v10 = o[j][2] * inv1, v11 = o[j][3] * inv1;
        __nv_bfloat16 h00 = __float2bfloat16_rn(v00);
        __nv_bfloat16 h01 = __float2bfloat16_rn(v01);
        __nv_bfloat16 h10 = __float2bfloat16_rn(v10);
        __nv_bfloat16 h11 = __float2bfloat16_rn(v11);
        *(uint32_t*)(oh + off0) = pack_bf2(h00, h01);
        *(uint32_t*)(oh + off1) = pack_bf2(h10, h11);
        *(uint32_t*)(ol + off0) = pack_bf2(
            __float2bfloat16_rn(v00 - __bfloat162float(h00)),
            __float2bfloat16_rn(v01 - __bfloat162float(h01)));
        *(uint32_t*)(ol + off1) = pack_bf2(
            __float2bfloat16_rn(v10 - __bfloat162float(h10)),
            __float2bfloat16_rn(v11 - __bfloat162float(h11)));
    }
}

// ---------------------------------------------------------------------------
extern "C" void kernel_launch(void* const* d_in, const int* in_sizes, int n_in,
                              void* d_out, int out_size)
{
    const float* x  = (const float*)d_in[0];
    const float* Wq = (const float*)d_in[1];
    const float* Wk = (const float*)d_in[2];
    const float* Wv = (const float*)d_in[3];
    const float* Wo = (const float*)d_in[4];
    float* out = (float*)d_out;

    float *gq, *gk, *gv;
    __nv_bfloat16 *xh, *xl, *wh, *wl, *ah, *al;
    cudaGetSymbolAddress((void**)&gq, g_q);
    cudaGetSymbolAddress((void**)&gk, g_k);
    cudaGetSymbolAddress((void**)&gv, g_v);
    cudaGetSymbolAddress((void**)&xh, g_xh);
    cudaGetSymbolAddress((void**)&xl, g_xl);
    cudaGetSymbolAddress((void**)&wh, g_wh);
    cudaGetSymbolAddress((void**)&wl, g_wl);
    cudaGetSymbolAddress((void**)&ah, g_ah);
    cudaGetSymbolAddress((void**)&al, g_al);

    cudaFuncSetAttribute(gemm_ps<0>, cudaFuncAttributeMaxDynamicSharedMemorySize, GEMM_SMEM);
    cudaFuncSetAttribute(gemm_ps<1>, cudaFuncAttributeMaxDynamicSharedMemorySize, GEMM_SMEM);
    cudaFuncSetAttribute(flash_mma,  cudaFuncAttributeMaxDynamicSharedMemorySize, FLASH_SMEM);

    // pre-split x and weights to bf16 hi/lo (once)
    split_f32<<<(MM * DM / 4 + 255) / 256, 256>>>(x, xh, xl, MM * DM / 4);
    split_w4<<<(int)(4 * WSZ / 4 + 255) / 256, 256>>>(Wq, Wk, Wv, Wo, wh, wl);

    dim3 gemm_grid(DM / 128, MM / 128);   // (8, 32)
    gemm_ps<1><<<gemm_grid, 256, GEMM_SMEM>>>(xh, xl, wh,           wl,           gq);
    gemm_ps<1><<<gemm_grid, 256, GEMM_SMEM>>>(xh, xl, wh + WSZ,     wl + WSZ,     gk);
    gemm_ps<1><<<gemm_grid, 256, GEMM_SMEM>>>(xh, xl, wh + 2 * WSZ, wl + 2 * WSZ, gv);

    flash_mma<<<dim3(TT / 128, NH, BB), 256, FLASH_SMEM>>>(gq, gk, gv, ah, al);

    gemm_ps<0><<<gemm_grid, 256, GEMM_SMEM>>>(ah, al, wh + 3 * WSZ, wl + 3 * WSZ, out);
}